// round 1
// baseline (speedup 1.0000x reference)
#include <cuda_runtime.h>
#include <cstdint>

#define S_LEN 4096
#define HID   1024
#define NH    16
#define HD    64
#define QKV_W (3 * HID)   // 3072

// Scratch (device-global, no allocation)
__device__ float g_qkv[(size_t)S_LEN * QKV_W];   // [s, 3H]  (q | k | v)
__device__ float g_ctx[(size_t)S_LEN * HID];     // [s, H]

// ---------------------------------------------------------------------------
// NT SGEMM: C[M,N] = A[M,K] @ B[N,K]^T + bias[N]
// BM=BN=64, BK=16, 256 threads, 4x4 per thread, smem transposed with +1 pad.
// ---------------------------------------------------------------------------
template<int BM, int BN, int BK>
__global__ __launch_bounds__(256)
void sgemm_nt_bias(const float* __restrict__ A,
                   const float* __restrict__ B,
                   const float* __restrict__ bias,
                   float* __restrict__ C,
                   int M, int N, int K)
{
    __shared__ float As[BK * (BM + 1)];
    __shared__ float Bs[BK * (BN + 1)];

    const int tid = threadIdx.x;
    const int tx  = tid & 15;        // 0..15 -> 4 output cols
    const int ty  = tid >> 4;        // 0..15 -> 4 output rows
    const int m0  = blockIdx.y * BM;
    const int n0  = blockIdx.x * BN;

    // float4 loader: 256 threads x 1 float4 = 64 rows x 16 k
    const int lr = tid >> 2;         // 0..63 row in tile
    const int lk = (tid & 3) * 4;    // 0,4,8,12 k offset

    float acc[4][4] = {};

    for (int k0 = 0; k0 < K; k0 += BK) {
        float4 av = *(const float4*)(A + (size_t)(m0 + lr) * K + k0 + lk);
        float4 bv = *(const float4*)(B + (size_t)(n0 + lr) * K + k0 + lk);
        __syncthreads();   // previous compute done before overwrite
        As[(lk + 0) * (BM + 1) + lr] = av.x;
        As[(lk + 1) * (BM + 1) + lr] = av.y;
        As[(lk + 2) * (BM + 1) + lr] = av.z;
        As[(lk + 3) * (BM + 1) + lr] = av.w;
        Bs[(lk + 0) * (BN + 1) + lr] = bv.x;
        Bs[(lk + 1) * (BN + 1) + lr] = bv.y;
        Bs[(lk + 2) * (BN + 1) + lr] = bv.z;
        Bs[(lk + 3) * (BN + 1) + lr] = bv.w;
        __syncthreads();

        #pragma unroll
        for (int kk = 0; kk < BK; kk++) {
            float a[4], b[4];
            #pragma unroll
            for (int i = 0; i < 4; i++) a[i] = As[kk * (BM + 1) + ty * 4 + i];
            #pragma unroll
            for (int j = 0; j < 4; j++) b[j] = Bs[kk * (BN + 1) + tx * 4 + j];
            #pragma unroll
            for (int i = 0; i < 4; i++)
                #pragma unroll
                for (int j = 0; j < 4; j++)
                    acc[i][j] += a[i] * b[j];
        }
    }

    float4 bb = *(const float4*)(bias + n0 + tx * 4);
    #pragma unroll
    for (int i = 0; i < 4; i++) {
        int row = m0 + ty * 4 + i;
        float4 o;
        o.x = acc[i][0] + bb.x;
        o.y = acc[i][1] + bb.y;
        o.z = acc[i][2] + bb.z;
        o.w = acc[i][3] + bb.w;
        *(float4*)(C + (size_t)row * N + n0 + tx * 4) = o;
    }
}

// ---------------------------------------------------------------------------
// Flash attention fp32, causal. One CTA per (qtile=64 rows, head).
// smem (dynamic, PAD=65 stride): Qs[d][q], Ks[d][k] (transposed), Vs[k][d],
// Ps[q][k]. 256 threads, each owns a 4x4 output tile.
// ---------------------------------------------------------------------------
#define PAD 65

__global__ __launch_bounds__(256)
void attn_flash(const float* __restrict__ qkv, float* __restrict__ ctx)
{
    extern __shared__ float sm[];
    float* Qs = sm;                  // HD * PAD   (d-major: [d][qrow])
    float* Ks = Qs + HD * PAD;       // HD * PAD   (d-major: [d][kcol])
    float* Vs = Ks + HD * PAD;       // 64 * PAD   ([key][d])
    float* Ps = Vs + 64 * PAD;       // 64 * PAD   ([qrow][key])

    const int tid  = threadIdx.x;
    const int tx   = tid & 15;
    const int ty   = tid >> 4;
    const int qt   = blockIdx.x;     // 0..63
    const int head = blockIdx.y;     // 0..15
    const int hoff = head * HD;

    // Load Q tile transposed, fold in 1/sqrt(64) = 0.125
    for (int idx = tid; idx < 64 * HD; idx += 256) {
        int r = idx >> 6, d = idx & 63;
        Qs[d * PAD + r] =
            qkv[(size_t)(qt * 64 + r) * QKV_W + hoff + d] * 0.125f;
    }

    float acc[4][4] = {};
    float m_i[4], l_i[4];
    #pragma unroll
    for (int i = 0; i < 4; i++) { m_i[i] = -1e30f; l_i[i] = 0.0f; }

    const int q_base = qt * 64 + ty * 4;

    for (int kt = 0; kt <= qt; kt++) {
        __syncthreads();  // previous iter's smem reads done (also covers Q load)
        for (int idx = tid; idx < 64 * HD; idx += 256) {
            int r = idx >> 6, d = idx & 63;
            size_t g = (size_t)(kt * 64 + r) * QKV_W + hoff + d;
            Ks[d * PAD + r] = qkv[g + HID];        // K at col offset H
            Vs[r * PAD + d] = qkv[g + 2 * HID];    // V at col offset 2H
        }
        __syncthreads();

        // S tile: s[i][j] = sum_d Qs[d][ty4+i] * Ks[d][tx4+j]
        float s[4][4] = {};
        #pragma unroll
        for (int d = 0; d < HD; d++) {
            float a[4], b[4];
            #pragma unroll
            for (int i = 0; i < 4; i++) a[i] = Qs[d * PAD + ty * 4 + i];
            #pragma unroll
            for (int j = 0; j < 4; j++) b[j] = Ks[d * PAD + tx * 4 + j];
            #pragma unroll
            for (int i = 0; i < 4; i++)
                #pragma unroll
                for (int j = 0; j < 4; j++)
                    s[i][j] += a[i] * b[j];
        }

        // Causal mask only needed on the diagonal tile
        if (kt == qt) {
            #pragma unroll
            for (int i = 0; i < 4; i++)
                #pragma unroll
                for (int j = 0; j < 4; j++)
                    if (kt * 64 + tx * 4 + j > q_base + i) s[i][j] = -1e30f;
        }

        // Online softmax, per query row (reduce across the 16 tx lanes)
        #pragma unroll
        for (int i = 0; i < 4; i++) {
            float mt = fmaxf(fmaxf(s[i][0], s[i][1]), fmaxf(s[i][2], s[i][3]));
            #pragma unroll
            for (int off = 8; off; off >>= 1)
                mt = fmaxf(mt, __shfl_xor_sync(0xffffffffu, mt, off, 16));
            float mnew = fmaxf(m_i[i], mt);
            float corr = __expf(m_i[i] - mnew);
            float lt = 0.0f;
            #pragma unroll
            for (int j = 0; j < 4; j++) {
                s[i][j] = __expf(s[i][j] - mnew);
                lt += s[i][j];
            }
            #pragma unroll
            for (int off = 8; off; off >>= 1)
                lt += __shfl_xor_sync(0xffffffffu, lt, off, 16);
            l_i[i] = l_i[i] * corr + lt;
            m_i[i] = mnew;
            #pragma unroll
            for (int j = 0; j < 4; j++) {
                acc[i][j] *= corr;
                Ps[(ty * 4 + i) * PAD + tx * 4 + j] = s[i][j];
            }
        }
        __syncthreads();  // Ps visible to all

        // acc += P @ V : acc[i][j] += sum_ck Ps[row][ck] * Vs[ck][dcol]
        #pragma unroll
        for (int ck = 0; ck < 64; ck++) {
            float a[4], b[4];
            #pragma unroll
            for (int i = 0; i < 4; i++) a[i] = Ps[(ty * 4 + i) * PAD + ck];
            #pragma unroll
            for (int j = 0; j < 4; j++) b[j] = Vs[ck * PAD + tx * 4 + j];
            #pragma unroll
            for (int i = 0; i < 4; i++)
                #pragma unroll
                for (int j = 0; j < 4; j++)
                    acc[i][j] += a[i] * b[j];
        }
    }

    // Epilogue: divide by l, write ctx[s, head*64 + d]
    #pragma unroll
    for (int i = 0; i < 4; i++) {
        float inv = 1.0f / l_i[i];
        int row = qt * 64 + ty * 4 + i;
        #pragma unroll
        for (int j = 0; j < 4; j++)
            ctx[(size_t)row * HID + hoff + tx * 4 + j] = acc[i][j] * inv;
    }
}

// ---------------------------------------------------------------------------
// Launch
// ---------------------------------------------------------------------------
extern "C" void kernel_launch(void* const* d_in, const int* in_sizes, int n_in,
                              void* d_out, int out_size)
{
    const float* hidden  = (const float*)d_in[0];
    // d_in[1] = ltor_mask (pure causal; applied analytically)
    const float* w_qkv   = (const float*)d_in[2];
    const float* b_qkv   = (const float*)d_in[3];
    const float* w_dense = (const float*)d_in[4];
    const float* b_dense = (const float*)d_in[5];
    float* out = (float*)d_out;

    float* qkv = nullptr;
    float* ctx = nullptr;
    cudaGetSymbolAddress((void**)&qkv, g_qkv);
    cudaGetSymbolAddress((void**)&ctx, g_ctx);

    // 1) QKV projection: [4096,1024] @ [3072,1024]^T -> [4096,3072]
    {
        dim3 grid(QKV_W / 64, S_LEN / 64);
        sgemm_nt_bias<64, 64, 16><<<grid, 256>>>(
            hidden, w_qkv, b_qkv, qkv, S_LEN, QKV_W, HID);
    }

    // 2) Causal flash attention -> ctx [4096,1024]
    {
        const int smem_bytes = (2 * HD * PAD + 2 * 64 * PAD) * (int)sizeof(float);
        static_assert((2 * HD * PAD + 2 * 64 * PAD) * sizeof(float) == 66560, "");
        cudaFuncSetAttribute(attn_flash,
                             cudaFuncAttributeMaxDynamicSharedMemorySize,
                             smem_bytes);
        dim3 grid(S_LEN / 64, NH);
        attn_flash<<<grid, 256, smem_bytes>>>(qkv, ctx);
    }

    // 3) Dense projection: [4096,1024] @ [1024,1024]^T -> out
    {
        dim3 grid(HID / 64, S_LEN / 64);
        sgemm_nt_bias<64, 64, 16><<<grid, 256>>>(
            ctx, w_dense, b_dense, out, S_LEN, HID, HID);
    }
}

// round 2
// speedup vs baseline: 1.2898x; 1.2898x over previous
#include <cuda_runtime.h>
#include <cstdint>

#define S_LEN 4096
#define HID   1024
#define NH    16
#define HD    64
#define QKV_W (3 * HID)   // 3072

// Scratch (device-global, no allocation)
__device__ float g_qkv[(size_t)S_LEN * QKV_W];   // [s, 3H]  (q | k | v)
__device__ float g_ctx[(size_t)S_LEN * HID];     // [s, H]

// ---------------------------------------------------------------------------
// NT SGEMM: C[M,N] = A[M,K] @ B[N,K]^T + bias[N]
// BM=BN=128, BK=16, 256 threads, 8x8 per thread, LDS.128 fragments,
// register prefetch of next k-tile.
// ---------------------------------------------------------------------------
#define SGA 132   // smem row stride (floats), 16B-aligned, kills most conflicts

__global__ __launch_bounds__(256, 2)
void sgemm128(const float* __restrict__ A,
              const float* __restrict__ B,
              const float* __restrict__ bias,
              float* __restrict__ C,
              int M, int N, int K)
{
    __shared__ float As[16][SGA];
    __shared__ float Bs[16][SGA];

    const int tid = threadIdx.x;
    const int tx  = tid & 15;        // 0..15 -> 8 output cols
    const int ty  = tid >> 4;        // 0..15 -> 8 output rows
    const int m0  = blockIdx.y * 128;
    const int n0  = blockIdx.x * 128;

    // loader: 256 threads, each 2 float4 from A (rows lr, lr+64) and 2 from B
    const int lr = tid >> 2;         // 0..63
    const int lk = (tid & 3) * 4;    // 0,4,8,12

    const float* Ap0 = A + (size_t)(m0 + lr) * K + lk;
    const float* Ap1 = Ap0 + (size_t)64 * K;
    const float* Bp0 = B + (size_t)(n0 + lr) * K + lk;
    const float* Bp1 = Bp0 + (size_t)64 * K;

    float4 pa0 = *(const float4*)(Ap0);
    float4 pa1 = *(const float4*)(Ap1);
    float4 pb0 = *(const float4*)(Bp0);
    float4 pb1 = *(const float4*)(Bp1);

    float acc[8][8] = {};

    for (int k0 = 0; k0 < K; k0 += 16) {
        __syncthreads();   // previous tile's compute done before overwrite
        As[lk + 0][lr]      = pa0.x;  As[lk + 1][lr]      = pa0.y;
        As[lk + 2][lr]      = pa0.z;  As[lk + 3][lr]      = pa0.w;
        As[lk + 0][lr + 64] = pa1.x;  As[lk + 1][lr + 64] = pa1.y;
        As[lk + 2][lr + 64] = pa1.z;  As[lk + 3][lr + 64] = pa1.w;
        Bs[lk + 0][lr]      = pb0.x;  Bs[lk + 1][lr]      = pb0.y;
        Bs[lk + 2][lr]      = pb0.z;  Bs[lk + 3][lr]      = pb0.w;
        Bs[lk + 0][lr + 64] = pb1.x;  Bs[lk + 1][lr + 64] = pb1.y;
        Bs[lk + 2][lr + 64] = pb1.z;  Bs[lk + 3][lr + 64] = pb1.w;
        __syncthreads();

        if (k0 + 16 < K) {
            pa0 = *(const float4*)(Ap0 + k0 + 16);
            pa1 = *(const float4*)(Ap1 + k0 + 16);
            pb0 = *(const float4*)(Bp0 + k0 + 16);
            pb1 = *(const float4*)(Bp1 + k0 + 16);
        }

        #pragma unroll
        for (int kk = 0; kk < 16; kk++) {
            float4 ar0 = *(const float4*)&As[kk][ty * 8];
            float4 ar1 = *(const float4*)&As[kk][ty * 8 + 4];
            float4 br0 = *(const float4*)&Bs[kk][tx * 8];
            float4 br1 = *(const float4*)&Bs[kk][tx * 8 + 4];
            float a[8] = {ar0.x, ar0.y, ar0.z, ar0.w, ar1.x, ar1.y, ar1.z, ar1.w};
            float b[8] = {br0.x, br0.y, br0.z, br0.w, br1.x, br1.y, br1.z, br1.w};
            #pragma unroll
            for (int i = 0; i < 8; i++)
                #pragma unroll
                for (int j = 0; j < 8; j++)
                    acc[i][j] += a[i] * b[j];
        }
    }

    float4 bb0 = *(const float4*)(bias + n0 + tx * 8);
    float4 bb1 = *(const float4*)(bias + n0 + tx * 8 + 4);
    #pragma unroll
    for (int i = 0; i < 8; i++) {
        float* Crow = C + (size_t)(m0 + ty * 8 + i) * N + n0 + tx * 8;
        float4 o0, o1;
        o0.x = acc[i][0] + bb0.x;  o0.y = acc[i][1] + bb0.y;
        o0.z = acc[i][2] + bb0.z;  o0.w = acc[i][3] + bb0.w;
        o1.x = acc[i][4] + bb1.x;  o1.y = acc[i][5] + bb1.y;
        o1.z = acc[i][6] + bb1.z;  o1.w = acc[i][7] + bb1.w;
        *(float4*)(Crow)     = o0;
        *(float4*)(Crow + 4) = o1;
    }
}

// ---------------------------------------------------------------------------
// Flash attention fp32, causal. CTA = (128 query rows, 1 head), 256 threads,
// 8x4 per thread. All smem traffic via LDS.128/STS.128.
// smem: Qs[d][q] 64x132, Ks[d][k] 64x68, Vs[k][d] 64x68, Ps[q][k] 128x68.
// ---------------------------------------------------------------------------
#define PQ 132
#define PK 68

__global__ __launch_bounds__(256, 2)
void attn_flash(const float* __restrict__ qkv, float* __restrict__ ctx)
{
    extern __shared__ float sm[];
    float* Qs = sm;                   // 64 * 132
    float* Ks = Qs + 64 * PQ;         // 64 * 68
    float* Vs = Ks + 64 * PK;         // 64 * 68
    float* Ps = Vs + 64 * PK;         // 128 * 68

    const int tid  = threadIdx.x;
    const int tx   = tid & 15;        // key/d column group (4 wide)
    const int ty   = tid >> 4;        // query row group (8 rows)
    const int qt   = 31 - blockIdx.x; // heavy tiles first
    const int head = blockIdx.y;
    const int hoff = head * HD;

    // Load Q tile (128 rows), transpose into Qs[d][r], fold 1/sqrt(64)
    {
        #pragma unroll
        for (int it = 0; it < 8; it++) {
            int idx = tid + it * 256;        // 0..2047
            int r  = idx >> 4;               // 0..127
            int c4 = (idx & 15) * 4;         // 0..60
            float4 v = *(const float4*)(qkv + (size_t)(qt * 128 + r) * QKV_W + hoff + c4);
            Qs[(c4 + 0) * PQ + r] = v.x * 0.125f;
            Qs[(c4 + 1) * PQ + r] = v.y * 0.125f;
            Qs[(c4 + 2) * PQ + r] = v.z * 0.125f;
            Qs[(c4 + 3) * PQ + r] = v.w * 0.125f;
        }
    }

    float acc[8][4] = {};
    float m_i[8], l_i[8];
    #pragma unroll
    for (int i = 0; i < 8; i++) { m_i[i] = -1e30f; l_i[i] = 0.0f; }

    const int kt_max = 2 * qt + 1;

    for (int kt = 0; kt <= kt_max; kt++) {
        __syncthreads();  // prev PV reads done; also covers Q-load on iter 0

        // Load K,V tile (64 rows x 64 d), 4 float4 each
        #pragma unroll
        for (int it = 0; it < 4; it++) {
            int idx = tid + it * 256;        // 0..1023
            int r  = idx >> 4;               // 0..63
            int c4 = (idx & 15) * 4;
            size_t g = (size_t)(kt * 64 + r) * QKV_W + hoff + c4;
            float4 kv = *(const float4*)(qkv + g + HID);
            float4 vv = *(const float4*)(qkv + g + 2 * HID);
            Ks[(c4 + 0) * PK + r] = kv.x;
            Ks[(c4 + 1) * PK + r] = kv.y;
            Ks[(c4 + 2) * PK + r] = kv.z;
            Ks[(c4 + 3) * PK + r] = kv.w;
            *(float4*)&Vs[r * PK + c4] = vv;
        }
        __syncthreads();

        // S tile: s[i][j] = sum_d Qs[d][ty8+i] * Ks[d][tx4+j]
        float s[8][4] = {};
        #pragma unroll
        for (int d = 0; d < HD; d++) {
            float4 a0 = *(const float4*)&Qs[d * PQ + ty * 8];
            float4 a1 = *(const float4*)&Qs[d * PQ + ty * 8 + 4];
            float4 bv = *(const float4*)&Ks[d * PK + tx * 4];
            float a[8] = {a0.x, a0.y, a0.z, a0.w, a1.x, a1.y, a1.z, a1.w};
            float b[4] = {bv.x, bv.y, bv.z, bv.w};
            #pragma unroll
            for (int i = 0; i < 8; i++)
                #pragma unroll
                for (int j = 0; j < 4; j++)
                    s[i][j] += a[i] * b[j];
        }

        // Causal mask (only the last two key tiles can cross the diagonal)
        if (kt >= 2 * qt) {
            #pragma unroll
            for (int i = 0; i < 8; i++) {
                int qrow = qt * 128 + ty * 8 + i;
                #pragma unroll
                for (int j = 0; j < 4; j++)
                    if (kt * 64 + tx * 4 + j > qrow) s[i][j] = -1e30f;
            }
        }

        // Online softmax per row (reduce across the 16 tx lanes)
        #pragma unroll
        for (int i = 0; i < 8; i++) {
            float mt = fmaxf(fmaxf(s[i][0], s[i][1]), fmaxf(s[i][2], s[i][3]));
            #pragma unroll
            for (int off = 8; off; off >>= 1)
                mt = fmaxf(mt, __shfl_xor_sync(0xffffffffu, mt, off, 16));
            float mnew = fmaxf(m_i[i], mt);
            float corr = __expf(m_i[i] - mnew);
            float lt = 0.0f;
            #pragma unroll
            for (int j = 0; j < 4; j++) {
                s[i][j] = __expf(s[i][j] - mnew);
                lt += s[i][j];
            }
            #pragma unroll
            for (int off = 8; off; off >>= 1)
                lt += __shfl_xor_sync(0xffffffffu, lt, off, 16);
            l_i[i] = l_i[i] * corr + lt;
            m_i[i] = mnew;
            #pragma unroll
            for (int j = 0; j < 4; j++) acc[i][j] *= corr;
            float4 sv = make_float4(s[i][0], s[i][1], s[i][2], s[i][3]);
            *(float4*)&Ps[(ty * 8 + i) * PK + tx * 4] = sv;
        }
        __syncthreads();  // Ps visible

        // acc += P @ V, 4 keys per step
        #pragma unroll
        for (int c0 = 0; c0 < 64; c0 += 4) {
            float pa[8][4];
            #pragma unroll
            for (int i = 0; i < 8; i++) {
                float4 t = *(const float4*)&Ps[(ty * 8 + i) * PK + c0];
                pa[i][0] = t.x; pa[i][1] = t.y; pa[i][2] = t.z; pa[i][3] = t.w;
            }
            #pragma unroll
            for (int cc = 0; cc < 4; cc++) {
                float4 bv = *(const float4*)&Vs[(c0 + cc) * PK + tx * 4];
                float b[4] = {bv.x, bv.y, bv.z, bv.w};
                #pragma unroll
                for (int i = 0; i < 8; i++)
                    #pragma unroll
                    for (int j = 0; j < 4; j++)
                        acc[i][j] += pa[i][cc] * b[j];
            }
        }
    }

    // Epilogue
    #pragma unroll
    for (int i = 0; i < 8; i++) {
        float inv = 1.0f / l_i[i];
        int row = qt * 128 + ty * 8 + i;
        float4 o = make_float4(acc[i][0] * inv, acc[i][1] * inv,
                               acc[i][2] * inv, acc[i][3] * inv);
        *(float4*)(ctx + (size_t)row * HID + hoff + tx * 4) = o;
    }
}

// ---------------------------------------------------------------------------
// Launch
// ---------------------------------------------------------------------------
extern "C" void kernel_launch(void* const* d_in, const int* in_sizes, int n_in,
                              void* d_out, int out_size)
{
    const float* hidden  = (const float*)d_in[0];
    // d_in[1] = ltor_mask (pure causal; applied analytically)
    const float* w_qkv   = (const float*)d_in[2];
    const float* b_qkv   = (const float*)d_in[3];
    const float* w_dense = (const float*)d_in[4];
    const float* b_dense = (const float*)d_in[5];
    float* out = (float*)d_out;

    float* qkv = nullptr;
    float* ctx = nullptr;
    cudaGetSymbolAddress((void**)&qkv, g_qkv);
    cudaGetSymbolAddress((void**)&ctx, g_ctx);

    // 1) QKV projection: [4096,1024] @ [3072,1024]^T -> [4096,3072]
    {
        dim3 grid(QKV_W / 128, S_LEN / 128);
        sgemm128<<<grid, 256>>>(hidden, w_qkv, b_qkv, qkv, S_LEN, QKV_W, HID);
    }

    // 2) Causal flash attention -> ctx [4096,1024]
    {
        const int smem_bytes = (64 * PQ + 2 * 64 * PK + 128 * PK) * (int)sizeof(float);
        static_assert((64 * PQ + 2 * 64 * PK + 128 * PK) * sizeof(float) == 103424, "");
        cudaFuncSetAttribute(attn_flash,
                             cudaFuncAttributeMaxDynamicSharedMemorySize,
                             smem_bytes);
        dim3 grid(S_LEN / 128, NH);
        attn_flash<<<grid, 256, smem_bytes>>>(qkv, ctx);
    }

    // 3) Dense projection: [4096,1024] @ [1024,1024]^T -> out
    {
        dim3 grid(HID / 128, S_LEN / 128);
        sgemm128<<<grid, 256>>>(ctx, w_dense, b_dense, out, S_LEN, HID, HID);
    }
}

// round 4
// speedup vs baseline: 1.4975x; 1.1610x over previous
#include <cuda_runtime.h>
#include <cstdint>

#define S_LEN 4096
#define HID   1024
#define NH    16
#define HD    64
#define QKV_W (3 * HID)   // 3072

// Scratch (device-global, no allocation)
__device__ float g_qkv[(size_t)S_LEN * QKV_W];   // [s, 3H]  (q | k | v)
__device__ float g_ctx[(size_t)S_LEN * HID];     // [s, H]

// ===========================================================================
// Split-bf16 helpers
// ===========================================================================
// cvt.rn.bf16x2.f32 d, a, b  ->  d.hi = bf16(a), d.lo = bf16(b)
__device__ __forceinline__ void split_pack(float4 v, uint2& hi, uint2& lo) {
    uint32_t h01, h23;
    asm("cvt.rn.bf16x2.f32 %0, %1, %2;" : "=r"(h01) : "f"(v.y), "f"(v.x));
    asm("cvt.rn.bf16x2.f32 %0, %1, %2;" : "=r"(h23) : "f"(v.w), "f"(v.z));
    float hx = __uint_as_float(h01 << 16);
    float hy = __uint_as_float(h01 & 0xFFFF0000u);
    float hz = __uint_as_float(h23 << 16);
    float hw = __uint_as_float(h23 & 0xFFFF0000u);
    uint32_t l01, l23;
    asm("cvt.rn.bf16x2.f32 %0, %1, %2;" : "=r"(l01) : "f"(v.y - hy), "f"(v.x - hx));
    asm("cvt.rn.bf16x2.f32 %0, %1, %2;" : "=r"(l23) : "f"(v.w - hw), "f"(v.z - hz));
    hi = make_uint2(h01, h23);
    lo = make_uint2(l01, l23);
}

__device__ __forceinline__ void mma16816(float* c, const uint32_t* a,
                                         uint32_t b0, uint32_t b1) {
    asm volatile(
        "mma.sync.aligned.m16n8k16.row.col.f32.bf16.bf16.f32 "
        "{%0,%1,%2,%3},{%4,%5,%6,%7},{%8,%9},{%0,%1,%2,%3};"
        : "+f"(c[0]), "+f"(c[1]), "+f"(c[2]), "+f"(c[3])
        : "r"(a[0]), "r"(a[1]), "r"(a[2]), "r"(a[3]), "r"(b0), "r"(b1));
}

// ===========================================================================
// HMMA split-bf16 NT GEMM: C[M,N] = A[M,K] @ B[N,K]^T + bias[N]
// CTA 128x128, 8 warps of 64x32, K-chunk 64 staged as bf16 hi/lo in smem.
// smem row stride 72 halves (144 B) -> conflict-free fragment LDS.
// ===========================================================================
#define SST 72                       // halves per smem row
#define TILE_HALVES (128 * SST)      // 9216 halves = 18432 B per buffer
#define GEMM_SMEM (4 * TILE_HALVES * 2)   // 73728 B

__global__ __launch_bounds__(256, 2)
void gemm_hmma(const float* __restrict__ A, const float* __restrict__ B,
               const float* __restrict__ bias, float* __restrict__ C,
               int M, int N, int K)
{
    extern __shared__ uint16_t sm16[];
    uint16_t* Ah = sm16;
    uint16_t* Al = Ah + TILE_HALVES;
    uint16_t* Bh = Al + TILE_HALVES;
    uint16_t* Bl = Bh + TILE_HALVES;

    const int tid  = threadIdx.x;
    const int lane = tid & 31;
    const int warp = tid >> 5;
    const int wm   = warp & 1;       // 2 warps along M (64 rows each)
    const int wn   = warp >> 1;      // 4 warps along N (32 cols each)
    const int g    = lane >> 2;      // 0..7
    const int t    = lane & 3;       // 0..3
    const int m0   = blockIdx.y * 128;
    const int n0   = blockIdx.x * 128;

    // loader mapping: thread -> row r (0..127), col base cb (0 or 32)
    const int r  = tid >> 1;
    const int cb = (tid & 1) * 32;
    const float* Ap = A + (size_t)(m0 + r) * K + cb;
    const float* Bp = B + (size_t)(n0 + r) * K + cb;

    float acc[4][4][4];
    #pragma unroll
    for (int mt = 0; mt < 4; mt++)
        #pragma unroll
        for (int nt = 0; nt < 4; nt++)
            #pragma unroll
            for (int e = 0; e < 4; e++) acc[mt][nt][e] = 0.0f;

    const int nchunk = K >> 6;
    for (int ch = 0; ch < nchunk; ch++) {
        __syncthreads();   // prior chunk's MMA reads done before overwrite
        #pragma unroll
        for (int q = 0; q < 8; q++) {
            float4 va = *(const float4*)(Ap + ch * 64 + q * 4);
            uint2 hi, lo;
            split_pack(va, hi, lo);
            *(uint2*)&Ah[r * SST + cb + q * 4] = hi;
            *(uint2*)&Al[r * SST + cb + q * 4] = lo;
            float4 vb = *(const float4*)(Bp + ch * 64 + q * 4);
            split_pack(vb, hi, lo);
            *(uint2*)&Bh[r * SST + cb + q * 4] = hi;
            *(uint2*)&Bl[r * SST + cb + q * 4] = lo;
        }
        __syncthreads();

        #pragma unroll
        for (int kk = 0; kk < 64; kk += 16) {
            uint32_t ah[4][4], al[4][4];
            #pragma unroll
            for (int mt = 0; mt < 4; mt++) {
                int row = wm * 64 + mt * 16;
                int o00 = (row + g) * SST + kk + 2 * t;
                int o10 = (row + g + 8) * SST + kk + 2 * t;
                ah[mt][0] = *(const uint32_t*)&Ah[o00];
                ah[mt][1] = *(const uint32_t*)&Ah[o10];
                ah[mt][2] = *(const uint32_t*)&Ah[o00 + 8];
                ah[mt][3] = *(const uint32_t*)&Ah[o10 + 8];
                al[mt][0] = *(const uint32_t*)&Al[o00];
                al[mt][1] = *(const uint32_t*)&Al[o10];
                al[mt][2] = *(const uint32_t*)&Al[o00 + 8];
                al[mt][3] = *(const uint32_t*)&Al[o10 + 8];
            }
            #pragma unroll
            for (int nt = 0; nt < 4; nt++) {
                int col = wn * 32 + nt * 8;
                int ob  = (col + g) * SST + kk + 2 * t;
                uint32_t bh0 = *(const uint32_t*)&Bh[ob];
                uint32_t bh1 = *(const uint32_t*)&Bh[ob + 8];
                uint32_t bl0 = *(const uint32_t*)&Bl[ob];
                uint32_t bl1 = *(const uint32_t*)&Bl[ob + 8];
                #pragma unroll
                for (int mt = 0; mt < 4; mt++) {
                    mma16816(acc[mt][nt], ah[mt], bh0, bh1);
                    mma16816(acc[mt][nt], ah[mt], bl0, bl1);
                    mma16816(acc[mt][nt], al[mt], bh0, bh1);
                }
            }
        }
    }

    // Epilogue: c0=(g,2t) c1=(g,2t+1) c2=(g+8,2t) c3=(g+8,2t+1)
    #pragma unroll
    for (int nt = 0; nt < 4; nt++) {
        int col = n0 + wn * 32 + nt * 8 + 2 * t;
        float2 b2 = *(const float2*)(bias + col);
        #pragma unroll
        for (int mt = 0; mt < 4; mt++) {
            int row = m0 + wm * 64 + mt * 16 + g;
            float2 o0 = make_float2(acc[mt][nt][0] + b2.x, acc[mt][nt][1] + b2.y);
            float2 o1 = make_float2(acc[mt][nt][2] + b2.x, acc[mt][nt][3] + b2.y);
            *(float2*)(C + (size_t)row * N + col)       = o0;
            *(float2*)(C + (size_t)(row + 8) * N + col) = o1;
        }
    }
}

// ---------------------------------------------------------------------------
// Flash attention fp32, causal (unchanged from R2 — known good).
// ---------------------------------------------------------------------------
#define PQ 132
#define PK 68

__global__ __launch_bounds__(256, 2)
void attn_flash(const float* __restrict__ qkv, float* __restrict__ ctx)
{
    extern __shared__ float sm[];
    float* Qs = sm;                   // 64 * 132
    float* Ks = Qs + 64 * PQ;         // 64 * 68
    float* Vs = Ks + 64 * PK;         // 64 * 68
    float* Ps = Vs + 64 * PK;         // 128 * 68

    const int tid  = threadIdx.x;
    const int tx   = tid & 15;
    const int ty   = tid >> 4;
    const int qt   = 31 - blockIdx.x; // heavy tiles first
    const int head = blockIdx.y;
    const int hoff = head * HD;

    #pragma unroll
    for (int it = 0; it < 8; it++) {
        int idx = tid + it * 256;
        int rr = idx >> 4;
        int c4 = (idx & 15) * 4;
        float4 v = *(const float4*)(qkv + (size_t)(qt * 128 + rr) * QKV_W + hoff + c4);
        Qs[(c4 + 0) * PQ + rr] = v.x * 0.125f;
        Qs[(c4 + 1) * PQ + rr] = v.y * 0.125f;
        Qs[(c4 + 2) * PQ + rr] = v.z * 0.125f;
        Qs[(c4 + 3) * PQ + rr] = v.w * 0.125f;
    }

    float acc[8][4] = {};
    float m_i[8], l_i[8];
    #pragma unroll
    for (int i = 0; i < 8; i++) { m_i[i] = -1e30f; l_i[i] = 0.0f; }

    const int kt_max = 2 * qt + 1;

    for (int kt = 0; kt <= kt_max; kt++) {
        __syncthreads();

        #pragma unroll
        for (int it = 0; it < 4; it++) {
            int idx = tid + it * 256;
            int rr = idx >> 4;
            int c4 = (idx & 15) * 4;
            size_t gg = (size_t)(kt * 64 + rr) * QKV_W + hoff + c4;
            float4 kv = *(const float4*)(qkv + gg + HID);
            float4 vv = *(const float4*)(qkv + gg + 2 * HID);
            Ks[(c4 + 0) * PK + rr] = kv.x;
            Ks[(c4 + 1) * PK + rr] = kv.y;
            Ks[(c4 + 2) * PK + rr] = kv.z;
            Ks[(c4 + 3) * PK + rr] = kv.w;
            *(float4*)&Vs[rr * PK + c4] = vv;
        }
        __syncthreads();

        float s[8][4] = {};
        #pragma unroll
        for (int d = 0; d < HD; d++) {
            float4 a0 = *(const float4*)&Qs[d * PQ + ty * 8];
            float4 a1 = *(const float4*)&Qs[d * PQ + ty * 8 + 4];
            float4 bv = *(const float4*)&Ks[d * PK + tx * 4];
            float a[8] = {a0.x, a0.y, a0.z, a0.w, a1.x, a1.y, a1.z, a1.w};
            float b[4] = {bv.x, bv.y, bv.z, bv.w};
            #pragma unroll
            for (int i = 0; i < 8; i++)
                #pragma unroll
                for (int j = 0; j < 4; j++)
                    s[i][j] += a[i] * b[j];
        }

        if (kt >= 2 * qt) {
            #pragma unroll
            for (int i = 0; i < 8; i++) {
                int qrow = qt * 128 + ty * 8 + i;
                #pragma unroll
                for (int j = 0; j < 4; j++)
                    if (kt * 64 + tx * 4 + j > qrow) s[i][j] = -1e30f;
            }
        }

        #pragma unroll
        for (int i = 0; i < 8; i++) {
            float mt = fmaxf(fmaxf(s[i][0], s[i][1]), fmaxf(s[i][2], s[i][3]));
            #pragma unroll
            for (int off = 8; off; off >>= 1)
                mt = fmaxf(mt, __shfl_xor_sync(0xffffffffu, mt, off, 16));
            float mnew = fmaxf(m_i[i], mt);
            float corr = __expf(m_i[i] - mnew);
            float lt = 0.0f;
            #pragma unroll
            for (int j = 0; j < 4; j++) {
                s[i][j] = __expf(s[i][j] - mnew);
                lt += s[i][j];
            }
            #pragma unroll
            for (int off = 8; off; off >>= 1)
                lt += __shfl_xor_sync(0xffffffffu, lt, off, 16);
            l_i[i] = l_i[i] * corr + lt;
            m_i[i] = mnew;
            #pragma unroll
            for (int j = 0; j < 4; j++) acc[i][j] *= corr;
            float4 sv = make_float4(s[i][0], s[i][1], s[i][2], s[i][3]);
            *(float4*)&Ps[(ty * 8 + i) * PK + tx * 4] = sv;
        }
        __syncthreads();

        #pragma unroll
        for (int c0 = 0; c0 < 64; c0 += 4) {
            float pa[8][4];
            #pragma unroll
            for (int i = 0; i < 8; i++) {
                float4 tt = *(const float4*)&Ps[(ty * 8 + i) * PK + c0];
                pa[i][0] = tt.x; pa[i][1] = tt.y; pa[i][2] = tt.z; pa[i][3] = tt.w;
            }
            #pragma unroll
            for (int cc = 0; cc < 4; cc++) {
                float4 bv = *(const float4*)&Vs[(c0 + cc) * PK + tx * 4];
                float b[4] = {bv.x, bv.y, bv.z, bv.w};
                #pragma unroll
                for (int i = 0; i < 8; i++)
                    #pragma unroll
                    for (int j = 0; j < 4; j++)
                        acc[i][j] += pa[i][cc] * b[j];
            }
        }
    }

    #pragma unroll
    for (int i = 0; i < 8; i++) {
        float inv = 1.0f / l_i[i];
        int row = qt * 128 + ty * 8 + i;
        float4 o = make_float4(acc[i][0] * inv, acc[i][1] * inv,
                               acc[i][2] * inv, acc[i][3] * inv);
        *(float4*)(ctx + (size_t)row * HID + hoff + tx * 4) = o;
    }
}

// ---------------------------------------------------------------------------
// Launch
// ---------------------------------------------------------------------------
extern "C" void kernel_launch(void* const* d_in, const int* in_sizes, int n_in,
                              void* d_out, int out_size)
{
    const float* hidden  = (const float*)d_in[0];
    // d_in[1] = ltor_mask (pure causal; applied analytically)
    const float* w_qkv   = (const float*)d_in[2];
    const float* b_qkv   = (const float*)d_in[3];
    const float* w_dense = (const float*)d_in[4];
    const float* b_dense = (const float*)d_in[5];
    float* out = (float*)d_out;

    float* qkv = nullptr;
    float* ctx = nullptr;
    cudaGetSymbolAddress((void**)&qkv, g_qkv);
    cudaGetSymbolAddress((void**)&ctx, g_ctx);

    cudaFuncSetAttribute(gemm_hmma, cudaFuncAttributeMaxDynamicSharedMemorySize,
                         GEMM_SMEM);

    // 1) QKV projection: [4096,1024] @ [3072,1024]^T -> [4096,3072]
    {
        dim3 grid(QKV_W / 128, S_LEN / 128);
        gemm_hmma<<<grid, 256, GEMM_SMEM>>>(hidden, w_qkv, b_qkv, qkv,
                                            S_LEN, QKV_W, HID);
    }

    // 2) Causal flash attention -> ctx [4096,1024]
    {
        const int smem_bytes = (64 * PQ + 2 * 64 * PK + 128 * PK) * (int)sizeof(float);
        cudaFuncSetAttribute(attn_flash,
                             cudaFuncAttributeMaxDynamicSharedMemorySize,
                             smem_bytes);
        dim3 grid(S_LEN / 128, NH);
        attn_flash<<<grid, 256, smem_bytes>>>(qkv, ctx);
    }

    // 3) Dense projection: [4096,1024] @ [1024,1024]^T -> out
    {
        dim3 grid(HID / 128, S_LEN / 128);
        gemm_hmma<<<grid, 256, GEMM_SMEM>>>(ctx, w_dense, b_dense, out,
                                            S_LEN, HID, HID);
    }
}

// round 6
// speedup vs baseline: 3.5091x; 2.3433x over previous
#include <cuda_runtime.h>
#include <cstdint>

#define S_LEN 4096
#define HID   1024
#define NH    16
#define HD    64
#define QKV_W (3 * HID)   // 3072

typedef unsigned short u16;

// Scratch (device-global, no allocation): split-bf16 hi/lo planes
__device__ u16 g_hid_h[(size_t)S_LEN * HID];
__device__ u16 g_hid_l[(size_t)S_LEN * HID];
__device__ u16 g_wqkv_h[(size_t)QKV_W * HID];
__device__ u16 g_wqkv_l[(size_t)QKV_W * HID];
__device__ u16 g_wd_h[(size_t)HID * HID];
__device__ u16 g_wd_l[(size_t)HID * HID];
__device__ u16 g_qkv_h[(size_t)S_LEN * QKV_W];
__device__ u16 g_qkv_l[(size_t)S_LEN * QKV_W];
__device__ u16 g_ctx_h[(size_t)S_LEN * HID];
__device__ u16 g_ctx_l[(size_t)S_LEN * HID];

// ===========================================================================
// Helpers
// ===========================================================================
__device__ __forceinline__ uint32_t smem_u32(const void* p) {
    uint32_t a;
    asm("{ .reg .u64 t; cvta.to.shared.u64 t, %1; cvt.u32.u64 %0, t; }"
        : "=r"(a) : "l"(p));
    return a;
}
#define CP16(dst, src) \
    asm volatile("cp.async.ca.shared.global [%0], [%1], 16;" \
                 :: "r"(dst), "l"(src) : "memory")
#define CP_COMMIT() asm volatile("cp.async.commit_group;" ::: "memory")
#define CP_WAIT1()  asm volatile("cp.async.wait_group 1;" ::: "memory")
#define CP_WAIT0()  asm volatile("cp.async.wait_group 0;" ::: "memory")

__device__ __forceinline__ void ldsm4(uint32_t* r, uint32_t a) {
    asm volatile("ldmatrix.sync.aligned.m8n8.x4.shared.b16 {%0,%1,%2,%3}, [%4];"
        : "=r"(r[0]), "=r"(r[1]), "=r"(r[2]), "=r"(r[3]) : "r"(a));
}
__device__ __forceinline__ void ldsm4t(uint32_t* r, uint32_t a) {
    asm volatile("ldmatrix.sync.aligned.m8n8.x4.trans.shared.b16 {%0,%1,%2,%3}, [%4];"
        : "=r"(r[0]), "=r"(r[1]), "=r"(r[2]), "=r"(r[3]) : "r"(a));
}
__device__ __forceinline__ void mma16816(float* c, const uint32_t* a,
                                         uint32_t b0, uint32_t b1) {
    asm volatile(
        "mma.sync.aligned.m16n8k16.row.col.f32.bf16.bf16.f32 "
        "{%0,%1,%2,%3},{%4,%5,%6,%7},{%8,%9},{%0,%1,%2,%3};"
        : "+f"(c[0]), "+f"(c[1]), "+f"(c[2]), "+f"(c[3])
        : "r"(a[0]), "r"(a[1]), "r"(a[2]), "r"(a[3]), "r"(b0), "r"(b1));
}
// pack (x,y) -> hi bf16x2 (lo half = x) + residual lo bf16x2
__device__ __forceinline__ void pack_split(float x, float y,
                                           uint32_t& hi, uint32_t& lo) {
    asm("cvt.rn.bf16x2.f32 %0, %1, %2;" : "=r"(hi) : "f"(y), "f"(x));
    float hx = __uint_as_float(hi << 16);
    float hy = __uint_as_float(hi & 0xFFFF0000u);
    asm("cvt.rn.bf16x2.f32 %0, %1, %2;" : "=r"(lo) : "f"(y - hy), "f"(x - hx));
}

// ===========================================================================
// Elementwise fp32 -> split bf16 hi/lo
// ===========================================================================
__global__ void split_f32(const float* __restrict__ src,
                          u16* __restrict__ hi, u16* __restrict__ lo, int n4)
{
    int i = blockIdx.x * blockDim.x + threadIdx.x;
    if (i >= n4) return;
    float4 v = ((const float4*)src)[i];
    uint32_t h0, l0, h1, l1;
    pack_split(v.x, v.y, h0, l0);
    pack_split(v.z, v.w, h1, l1);
    ((uint2*)hi)[i] = make_uint2(h0, h1);
    ((uint2*)lo)[i] = make_uint2(l0, l1);
}

// ===========================================================================
// HMMA NT GEMM on pre-split inputs. C = A @ B^T + bias.
// CTA 128x128, 8 warps (2x4), K-chunk 32, cp.async double buffer, ldmatrix.
// smem buffer: rows stride 40 halves (80 B) -> conflict-free ldmatrix.
// ===========================================================================
#define GBUF 5120                 // halves per buffer (128 rows * 40)
#define GSTG (4 * GBUF)           // halves per stage (Ah,Al,Bh,Bl)
#define GEMM_SMEM (2 * GSTG * 2)  // bytes = 81920

__global__ __launch_bounds__(256, 2)
void gemm_hmma(const u16* __restrict__ Ah_g, const u16* __restrict__ Al_g,
               const u16* __restrict__ Bh_g, const u16* __restrict__ Bl_g,
               const float* __restrict__ bias,
               float* __restrict__ Cf, u16* __restrict__ Ch, u16* __restrict__ Cl,
               int M, int N, int K, int split_out)
{
    extern __shared__ u16 sm[];
    const uint32_t sb = smem_u32(sm);

    const int tid  = threadIdx.x;
    const int lane = tid & 31;
    const int warp = tid >> 5;
    const int wm   = warp & 1;
    const int wn   = warp >> 1;
    const int g    = lane >> 2;
    const int t    = lane & 3;
    const int m0   = blockIdx.y * 128;
    const int n0   = blockIdx.x * 128;

    // ldmatrix lane address components
    const int la_row = lane & 15;
    const int la_col = (lane & 16) ? 8 : 0;
    const int lb_row = (lane & 7) + ((lane & 16) ? 8 : 0);
    const int lb_col = (lane & 8) ? 8 : 0;

    float acc[4][4][4];
    #pragma unroll
    for (int a = 0; a < 4; a++)
        #pragma unroll
        for (int b = 0; b < 4; b++)
            #pragma unroll
            for (int e = 0; e < 4; e++) acc[a][b][e] = 0.0f;

    const int nchunk = K >> 5;   // K/32

    auto load_stage = [&](int ch, int st) {
        const int k0 = ch * 32;
        const uint32_t sbase = sb + (st * GSTG) * 2;
        #pragma unroll
        for (int it = 0; it < 8; it++) {
            int c   = tid + it * 256;       // 0..2047
            int buf = c >> 9;               // 0..3
            int cc  = c & 511;
            int row = cc >> 2;
            int q   = cc & 3;
            const u16* src;
            if (buf == 0)      src = Ah_g + (size_t)(m0 + row) * K + k0 + q * 8;
            else if (buf == 1) src = Al_g + (size_t)(m0 + row) * K + k0 + q * 8;
            else if (buf == 2) src = Bh_g + (size_t)(n0 + row) * K + k0 + q * 8;
            else               src = Bl_g + (size_t)(n0 + row) * K + k0 + q * 8;
            uint32_t dst = sbase + (buf * GBUF + row * 40 + q * 8) * 2;
            CP16(dst, src);
        }
        CP_COMMIT();
    };

    load_stage(0, 0);

    for (int ch = 0; ch < nchunk; ch++) {
        const int st = ch & 1;
        if (ch + 1 < nchunk) load_stage(ch + 1, st ^ 1);
        if (ch + 1 < nchunk) CP_WAIT1(); else CP_WAIT0();
        __syncthreads();

        const uint32_t sbase = sb + (st * GSTG) * 2;
        #pragma unroll
        for (int kk = 0; kk < 32; kk += 16) {
            uint32_t ah[4][4], al[4][4];
            #pragma unroll
            for (int mt = 0; mt < 4; mt++) {
                uint32_t ra = sbase +
                    ((wm * 64 + mt * 16 + la_row) * 40 + kk + la_col) * 2;
                ldsm4(ah[mt], ra);
                ldsm4(al[mt], ra + GBUF * 2);
            }
            #pragma unroll
            for (int np = 0; np < 2; np++) {
                uint32_t bh[4], bl[4];
                uint32_t rb = sbase + 2 * GBUF * 2 +
                    ((wn * 32 + np * 16 + lb_row) * 40 + kk + lb_col) * 2;
                ldsm4(bh, rb);
                ldsm4(bl, rb + GBUF * 2);
                #pragma unroll
                for (int sub = 0; sub < 2; sub++) {
                    int nt = 2 * np + sub;
                    uint32_t b0h = bh[sub * 2], b1h = bh[sub * 2 + 1];
                    uint32_t b0l = bl[sub * 2], b1l = bl[sub * 2 + 1];
                    #pragma unroll
                    for (int mt = 0; mt < 4; mt++) {
                        mma16816(acc[mt][nt], ah[mt], b0h, b1h);
                        mma16816(acc[mt][nt], ah[mt], b0l, b1l);
                        mma16816(acc[mt][nt], al[mt], b0h, b1h);
                    }
                }
            }
        }
        __syncthreads();
    }

    // Epilogue
    #pragma unroll
    for (int nt = 0; nt < 4; nt++) {
        int col = n0 + wn * 32 + nt * 8 + 2 * t;
        float2 b2 = *(const float2*)(bias + col);
        #pragma unroll
        for (int mt = 0; mt < 4; mt++) {
            int r0 = m0 + wm * 64 + mt * 16 + g;
            float c0 = acc[mt][nt][0] + b2.x, c1 = acc[mt][nt][1] + b2.y;
            float c2 = acc[mt][nt][2] + b2.x, c3 = acc[mt][nt][3] + b2.y;
            if (split_out) {
                uint32_t h, l;
                pack_split(c0, c1, h, l);
                *(uint32_t*)&Ch[(size_t)r0 * N + col] = h;
                *(uint32_t*)&Cl[(size_t)r0 * N + col] = l;
                pack_split(c2, c3, h, l);
                *(uint32_t*)&Ch[(size_t)(r0 + 8) * N + col] = h;
                *(uint32_t*)&Cl[(size_t)(r0 + 8) * N + col] = l;
            } else {
                *(float2*)(Cf + (size_t)r0 * N + col)       = make_float2(c0, c1);
                *(float2*)(Cf + (size_t)(r0 + 8) * N + col) = make_float2(c2, c3);
            }
        }
    }
}

// ===========================================================================
// Tensor-core flash attention, causal, split-bf16, online softmax.
// CTA: 128 q-rows x 1 head, 8 warps (16 rows each), Bc=64 keys/iter.
// Q fragments register-resident; P stays in registers (acc layout == A-frag).
// smem: per stage Kh,Kl,Vh,Vl each 64 rows x 72-half stride.
// ===========================================================================
#define ABUF 4608                 // halves per buffer (64 * 72)
#define ASTG (4 * ABUF)
#define ATT_SMEM (2 * ASTG * 2)   // 73728 bytes

__global__ __launch_bounds__(256, 2)
void attn_tc(const u16* __restrict__ qh_g, const u16* __restrict__ ql_g,
             u16* __restrict__ ch_g, u16* __restrict__ cl_g)
{
    extern __shared__ u16 sm[];
    const uint32_t sb = smem_u32(sm);

    const int tid  = threadIdx.x;
    const int lane = tid & 31;
    const int warp = tid >> 5;
    const int g    = lane >> 2;
    const int t    = lane & 3;
    const int qt   = 31 - blockIdx.x;    // heavy tiles first
    const int head = blockIdx.y;
    const int hoff = head * HD;

    const int lb_row = (lane & 7) + ((lane & 16) ? 8 : 0);
    const int lb_col = (lane & 8) ? 8 : 0;

    const int qbase = qt * 128 + warp * 16;
    const int row_g0 = qbase + g;
    const int row_g1 = qbase + g + 8;

    // Q fragments (register resident): 4 k-steps x {a0..a3} x hi/lo
    uint32_t qh[4][4], ql[4][4];
    #pragma unroll
    for (int ks = 0; ks < 4; ks++) {
        size_t base = (size_t)row_g0 * QKV_W + hoff + ks * 16 + 2 * t;
        size_t base8 = base + (size_t)8 * QKV_W;
        qh[ks][0] = *(const uint32_t*)&qh_g[base];
        qh[ks][1] = *(const uint32_t*)&qh_g[base8];
        qh[ks][2] = *(const uint32_t*)&qh_g[base + 8];
        qh[ks][3] = *(const uint32_t*)&qh_g[base8 + 8];
        ql[ks][0] = *(const uint32_t*)&ql_g[base];
        ql[ks][1] = *(const uint32_t*)&ql_g[base8];
        ql[ks][2] = *(const uint32_t*)&ql_g[base + 8];
        ql[ks][3] = *(const uint32_t*)&ql_g[base8 + 8];
    }

    float oacc[8][4];
    #pragma unroll
    for (int d = 0; d < 8; d++)
        #pragma unroll
        for (int e = 0; e < 4; e++) oacc[d][e] = 0.0f;
    float m0 = -1e30f, m1 = -1e30f, l0 = 0.0f, l1 = 0.0f;

    const int ntile = 2 * qt + 2;

    auto load_stage = [&](int kt, int st) {
        const uint32_t sbase = sb + (st * ASTG) * 2;
        #pragma unroll
        for (int it = 0; it < 8; it++) {
            int c   = tid + it * 256;     // 0..2047
            int buf = c >> 9;             // 0:Kh 1:Kl 2:Vh 3:Vl
            int cc  = c & 511;
            int row = cc >> 3;            // 0..63
            int q   = cc & 7;             // 0..7 -> full 64 halves per row
            size_t go = (size_t)(kt * 64 + row) * QKV_W + hoff + q * 8
                      + ((buf < 2) ? HID : 2 * HID);
            const u16* src = ((buf & 1) ? ql_g : qh_g) + go;
            uint32_t dst = sbase + (buf * ABUF + row * 72 + q * 8) * 2;
            CP16(dst, src);
        }
        CP_COMMIT();
    };

    load_stage(0, 0);

    for (int kt = 0; kt < ntile; kt++) {
        const int st = kt & 1;
        if (kt + 1 < ntile) load_stage(kt + 1, st ^ 1);
        if (kt + 1 < ntile) CP_WAIT1(); else CP_WAIT0();
        __syncthreads();

        const uint32_t sbase = sb + (st * ASTG) * 2;

        // ---- S = Q K^T (split 3-term) ----
        float sacc[8][4];
        #pragma unroll
        for (int nt = 0; nt < 8; nt++)
            #pragma unroll
            for (int e = 0; e < 4; e++) sacc[nt][e] = 0.0f;

        #pragma unroll
        for (int ks = 0; ks < 4; ks++) {
            #pragma unroll
            for (int np = 0; np < 4; np++) {
                uint32_t bh[4], bl[4];
                uint32_t rk = sbase +
                    ((np * 16 + lb_row) * 72 + ks * 16 + lb_col) * 2;
                ldsm4(bh, rk);
                ldsm4(bl, rk + ABUF * 2);
                #pragma unroll
                for (int sub = 0; sub < 2; sub++) {
                    int nt = 2 * np + sub;
                    mma16816(sacc[nt], qh[ks], bh[sub * 2], bh[sub * 2 + 1]);
                    mma16816(sacc[nt], qh[ks], bl[sub * 2], bl[sub * 2 + 1]);
                    mma16816(sacc[nt], ql[ks], bh[sub * 2], bh[sub * 2 + 1]);
                }
            }
        }

        // ---- scale + causal mask ----
        #pragma unroll
        for (int nt = 0; nt < 8; nt++)
            #pragma unroll
            for (int e = 0; e < 4; e++) sacc[nt][e] *= 0.125f;
        if (kt >= 2 * qt) {
            #pragma unroll
            for (int nt = 0; nt < 8; nt++) {
                int c0 = kt * 64 + nt * 8 + 2 * t;
                if (c0 > row_g0)     sacc[nt][0] = -1e30f;
                if (c0 + 1 > row_g0) sacc[nt][1] = -1e30f;
                if (c0 > row_g1)     sacc[nt][2] = -1e30f;
                if (c0 + 1 > row_g1) sacc[nt][3] = -1e30f;
            }
        }

        // ---- online softmax (rows g and g+8; reduce over quad t=0..3) ----
        float mt0 = -1e30f, mt1 = -1e30f;
        #pragma unroll
        for (int nt = 0; nt < 8; nt++) {
            mt0 = fmaxf(mt0, fmaxf(sacc[nt][0], sacc[nt][1]));
            mt1 = fmaxf(mt1, fmaxf(sacc[nt][2], sacc[nt][3]));
        }
        mt0 = fmaxf(mt0, __shfl_xor_sync(0xffffffffu, mt0, 1));
        mt0 = fmaxf(mt0, __shfl_xor_sync(0xffffffffu, mt0, 2));
        mt1 = fmaxf(mt1, __shfl_xor_sync(0xffffffffu, mt1, 1));
        mt1 = fmaxf(mt1, __shfl_xor_sync(0xffffffffu, mt1, 2));
        float mn0 = fmaxf(m0, mt0), mn1 = fmaxf(m1, mt1);
        float cr0 = __expf(m0 - mn0), cr1 = __expf(m1 - mn1);
        float lt0 = 0.0f, lt1 = 0.0f;
        #pragma unroll
        for (int nt = 0; nt < 8; nt++) {
            sacc[nt][0] = __expf(sacc[nt][0] - mn0);
            sacc[nt][1] = __expf(sacc[nt][1] - mn0);
            sacc[nt][2] = __expf(sacc[nt][2] - mn1);
            sacc[nt][3] = __expf(sacc[nt][3] - mn1);
            lt0 += sacc[nt][0] + sacc[nt][1];
            lt1 += sacc[nt][2] + sacc[nt][3];
        }
        lt0 += __shfl_xor_sync(0xffffffffu, lt0, 1);
        lt0 += __shfl_xor_sync(0xffffffffu, lt0, 2);
        lt1 += __shfl_xor_sync(0xffffffffu, lt1, 1);
        lt1 += __shfl_xor_sync(0xffffffffu, lt1, 2);
        l0 = l0 * cr0 + lt0;  m0 = mn0;
        l1 = l1 * cr1 + lt1;  m1 = mn1;
        #pragma unroll
        for (int d = 0; d < 8; d++) {
            oacc[d][0] *= cr0; oacc[d][1] *= cr0;
            oacc[d][2] *= cr1; oacc[d][3] *= cr1;
        }

        // ---- O += P V (P from sacc registers; split 3-term) ----
        #pragma unroll
        for (int kc = 0; kc < 4; kc++) {
            uint32_t ph[4], pl[4];
            pack_split(sacc[2 * kc][0],     sacc[2 * kc][1],     ph[0], pl[0]);
            pack_split(sacc[2 * kc][2],     sacc[2 * kc][3],     ph[1], pl[1]);
            pack_split(sacc[2 * kc + 1][0], sacc[2 * kc + 1][1], ph[2], pl[2]);
            pack_split(sacc[2 * kc + 1][2], sacc[2 * kc + 1][3], ph[3], pl[3]);
            #pragma unroll
            for (int dp = 0; dp < 4; dp++) {
                uint32_t vh[4], vl[4];
                uint32_t rv = sbase + 2 * ABUF * 2 +
                    ((kc * 16 + lb_row) * 72 + dp * 16 + lb_col) * 2;
                ldsm4t(vh, rv);
                ldsm4t(vl, rv + ABUF * 2);
                mma16816(oacc[2 * dp],     ph, vh[0], vh[2]);
                mma16816(oacc[2 * dp],     ph, vl[0], vl[2]);
                mma16816(oacc[2 * dp],     pl, vh[0], vh[2]);
                mma16816(oacc[2 * dp + 1], ph, vh[1], vh[3]);
                mma16816(oacc[2 * dp + 1], ph, vl[1], vl[3]);
                mma16816(oacc[2 * dp + 1], pl, vh[1], vh[3]);
            }
        }
        __syncthreads();
    }

    // ---- epilogue: normalize, split, store ctx hi/lo ----
    float inv0 = 1.0f / l0, inv1 = 1.0f / l1;
    #pragma unroll
    for (int dt = 0; dt < 8; dt++) {
        int col = hoff + dt * 8 + 2 * t;
        uint32_t h, l;
        pack_split(oacc[dt][0] * inv0, oacc[dt][1] * inv0, h, l);
        *(uint32_t*)&ch_g[(size_t)row_g0 * HID + col] = h;
        *(uint32_t*)&cl_g[(size_t)row_g0 * HID + col] = l;
        pack_split(oacc[dt][2] * inv1, oacc[dt][3] * inv1, h, l);
        *(uint32_t*)&ch_g[(size_t)row_g1 * HID + col] = h;
        *(uint32_t*)&cl_g[(size_t)row_g1 * HID + col] = l;
    }
}

// ===========================================================================
// Launch
// ===========================================================================
extern "C" void kernel_launch(void* const* d_in, const int* in_sizes, int n_in,
                              void* d_out, int out_size)
{
    const float* hidden  = (const float*)d_in[0];
    // d_in[1] = ltor_mask (pure causal; applied analytically)
    const float* w_qkv   = (const float*)d_in[2];
    const float* b_qkv   = (const float*)d_in[3];
    const float* w_dense = (const float*)d_in[4];
    const float* b_dense = (const float*)d_in[5];
    float* out = (float*)d_out;

    u16 *hid_h, *hid_l, *wq_h, *wq_l, *wd_h, *wd_l, *qkv_h, *qkv_l, *ctx_h, *ctx_l;
    cudaGetSymbolAddress((void**)&hid_h, g_hid_h);
    cudaGetSymbolAddress((void**)&hid_l, g_hid_l);
    cudaGetSymbolAddress((void**)&wq_h,  g_wqkv_h);
    cudaGetSymbolAddress((void**)&wq_l,  g_wqkv_l);
    cudaGetSymbolAddress((void**)&wd_h,  g_wd_h);
    cudaGetSymbolAddress((void**)&wd_l,  g_wd_l);
    cudaGetSymbolAddress((void**)&qkv_h, g_qkv_h);
    cudaGetSymbolAddress((void**)&qkv_l, g_qkv_l);
    cudaGetSymbolAddress((void**)&ctx_h, g_ctx_h);
    cudaGetSymbolAddress((void**)&ctx_l, g_ctx_l);

    cudaFuncSetAttribute(gemm_hmma, cudaFuncAttributeMaxDynamicSharedMemorySize,
                         GEMM_SMEM);
    cudaFuncSetAttribute(attn_tc, cudaFuncAttributeMaxDynamicSharedMemorySize,
                         ATT_SMEM);

    // 0) split inputs to bf16 hi/lo
    {
        int n4;
        n4 = S_LEN * HID / 4;
        split_f32<<<(n4 + 255) / 256, 256>>>(hidden, hid_h, hid_l, n4);
        n4 = QKV_W * HID / 4;
        split_f32<<<(n4 + 255) / 256, 256>>>(w_qkv, wq_h, wq_l, n4);
        n4 = HID * HID / 4;
        split_f32<<<(n4 + 255) / 256, 256>>>(w_dense, wd_h, wd_l, n4);
    }

    // 1) QKV projection -> split qkv
    {
        dim3 grid(QKV_W / 128, S_LEN / 128);
        gemm_hmma<<<grid, 256, GEMM_SMEM>>>(hid_h, hid_l, wq_h, wq_l, b_qkv,
                                            nullptr, qkv_h, qkv_l,
                                            S_LEN, QKV_W, HID, 1);
    }

    // 2) Tensor-core causal flash attention -> split ctx
    {
        dim3 grid(S_LEN / 128, NH);
        attn_tc<<<grid, 256, ATT_SMEM>>>(qkv_h, qkv_l, ctx_h, ctx_l);
    }

    // 3) Dense projection -> fp32 out
    {
        dim3 grid(HID / 128, S_LEN / 128);
        gemm_hmma<<<grid, 256, GEMM_SMEM>>>(ctx_h, ctx_l, wd_h, wd_l, b_dense,
                                            out, nullptr, nullptr,
                                            S_LEN, HID, HID, 0);
    }
}